// round 8
// baseline (speedup 1.0000x reference)
#include <cuda_runtime.h>
#include <cuda_bf16.h>
#include <cstdint>

#define MAX_NODES 50000

__device__ float g_agg[MAX_NODES * 64];
__device__ float g_deg[MAX_NODES];
__device__ float g_P[MAX_NODES * 128];   // P[v] = feats[v] @ [W1e[0:64]||W1e[64:128]]

// ---------------- helpers ----------------
__device__ __forceinline__ void mma16816(float d[4], const uint32_t a[4],
                                         const uint32_t b[2]) {
    asm("mma.sync.aligned.m16n8k16.row.col.f32.bf16.bf16.f32 "
        "{%0,%1,%2,%3}, {%4,%5,%6,%7}, {%8,%9}, {%0,%1,%2,%3};"
        : "+f"(d[0]), "+f"(d[1]), "+f"(d[2]), "+f"(d[3])
        : "r"(a[0]), "r"(a[1]), "r"(a[2]), "r"(a[3]), "r"(b[0]), "r"(b[1]));
}

__device__ __forceinline__ void split2(float x0, float x1,
                                       uint32_t& uh, uint32_t& ul) {
    __nv_bfloat162 bh = __floats2bfloat162_rn(x0, x1);
    float2 back = __bfloat1622float2(bh);
    __nv_bfloat162 bl = __floats2bfloat162_rn(x0 - back.x, x1 - back.y);
    uh = *(uint32_t*)&bh;
    ul = *(uint32_t*)&bl;
}

__device__ __forceinline__ void red_add4(float* addr, float4 v) {
    asm volatile("red.global.add.v4.f32 [%0], {%1, %2, %3, %4};"
                 :: "l"(addr), "f"(v.x), "f"(v.y), "f"(v.z), "f"(v.w) : "memory");
}

// ---------------- kernel 0: zero scratch ----------------
__global__ void zero_kernel(int n_nodes) {
    int i = blockIdx.x * blockDim.x + threadIdx.x;
    int stride = gridDim.x * blockDim.x;
    int tot = n_nodes * 64;
    for (int k = i; k < tot; k += stride) g_agg[k] = 0.0f;
    for (int k = i; k < n_nodes; k += stride) g_deg[k] = 0.0f;
}

// ======================= P precompute kernel =======================
#define P_SA_HI 0u
#define P_SA_LO 18432u
#define P_SW_HI 36864u
#define P_SW_LO 55296u
#define P_SMEM  73728u

__global__ void __launch_bounds__(256, 2) pnode_kernel(
    const float* __restrict__ feats,
    const float* __restrict__ W1e,
    int n_nodes)
{
    extern __shared__ char smem[];
    uint32_t* sA_hi = (uint32_t*)(smem + P_SA_HI);
    uint32_t* sA_lo = (uint32_t*)(smem + P_SA_LO);
    uint32_t* sW_hi = (uint32_t*)(smem + P_SW_HI);
    uint32_t* sW_lo = (uint32_t*)(smem + P_SW_LO);

    int tid = threadIdx.x;
    for (int i = tid; i < 128 * 64; i += 256) {
        int n = i & 127, k = i >> 7;
        float w = (n < 64) ? W1e[k * 64 + n] : W1e[(64 + k) * 64 + (n - 64)];
        __nv_bfloat16 wh = __float2bfloat16_rn(w);
        __nv_bfloat16 wl = __float2bfloat16_rn(w - __bfloat162float(wh));
        ((__nv_bfloat16*)sW_hi)[n * 72 + k] = wh;
        ((__nv_bfloat16*)sW_lo)[n * 72 + k] = wl;
    }
    __syncthreads();

    const int warp = tid >> 5, lane = tid & 31;
    const int g = lane >> 2, t = lane & 3;
    const int wr = warp << 4;
    const int row = tid >> 1, half = tid & 1;

    int nTiles = (n_nodes + 127) >> 7;

    for (int tile = blockIdx.x; tile < nTiles; tile += gridDim.x) {
        int nbase = tile << 7;
        {
            int nr = nbase + row;
            int nid = nr < n_nodes ? nr : (n_nodes - 1);
            const float4* src = (const float4*)(feats + (size_t)nid * 64) + half * 8;
            #pragma unroll
            for (int cc = 0; cc < 4; cc++) {
                float4 va = src[cc * 2], vb = src[cc * 2 + 1];
                uint4 uh, ul;
                split2(va.x, va.y, uh.x, ul.x);
                split2(va.z, va.w, uh.y, ul.y);
                split2(vb.x, vb.y, uh.z, ul.z);
                split2(vb.z, vb.w, uh.w, ul.w);
                int col = half * 32 + cc * 8;
                int widx = row * 36 + (col >> 1);
                *(uint4*)(sA_hi + widx) = uh;
                *(uint4*)(sA_lo + widx) = ul;
            }
        }
        __syncwarp();

        float d[16][4];
        #pragma unroll
        for (int i = 0; i < 16; i++)
            #pragma unroll
            for (int j = 0; j < 4; j++) d[i][j] = 0.0f;

        #pragma unroll 1
        for (int kt = 0; kt < 4; kt++) {
            int ab = (wr + g) * 36 + kt * 8 + t;
            uint32_t ah[4], al[4];
            ah[0] = sA_hi[ab];       ah[1] = sA_hi[ab + 288];
            ah[2] = sA_hi[ab + 4];   ah[3] = sA_hi[ab + 292];
            al[0] = sA_lo[ab];       al[1] = sA_lo[ab + 288];
            al[2] = sA_lo[ab + 4];   al[3] = sA_lo[ab + 292];
            int bbase = g * 36 + kt * 8 + t;
            #pragma unroll
            for (int nt = 0; nt < 16; nt++) {
                int bb = bbase + nt * 288;
                uint32_t b2[2] = { sW_hi[bb], sW_hi[bb + 4] };
                mma16816(d[nt], ah, b2);
            }
            #pragma unroll
            for (int nt = 0; nt < 16; nt++) {
                int bb = bbase + nt * 288;
                uint32_t b2[2] = { sW_lo[bb], sW_lo[bb + 4] };
                mma16816(d[nt], ah, b2);
            }
            #pragma unroll
            for (int nt = 0; nt < 16; nt++) {
                int bb = bbase + nt * 288;
                uint32_t b2[2] = { sW_hi[bb], sW_hi[bb + 4] };
                mma16816(d[nt], al, b2);
            }
        }

        {
            int r0 = nbase + wr + g, r1 = r0 + 8;
            bool v0 = r0 < n_nodes, v1 = r1 < n_nodes;
            #pragma unroll
            for (int nt = 0; nt < 16; nt++) {
                int c0 = nt * 8 + 2 * t;
                if (v0) *(float2*)(g_P + (size_t)r0 * 128 + c0) =
                            make_float2(d[nt][0], d[nt][1]);
                if (v1) *(float2*)(g_P + (size_t)r1 * 128 + c0) =
                            make_float2(d[nt][2], d[nt][3]);
            }
        }
        __syncwarp();
    }
}

// ======================= edge kernel =======================
#define E_SA_HI   0u
#define E_SA_LO   18432u
#define E_SW1_HI  36864u
#define E_SW1_LO  46080u
#define E_SH_HI   55296u
#define E_SH_LO   73728u
#define E_SW2_HI  92160u
#define E_SW2_LO  101376u
#define E_BIAS1   110592u
#define E_BIAS2   110848u
#define E_SR      111104u
#define E_SC      111616u
#define E_SMEM    112128u

__global__ void __launch_bounds__(256, 2) edge_kernel(
    const float* __restrict__ feats,
    const int* __restrict__ edge_index,
    const float* __restrict__ edge_attr,
    const float* __restrict__ W1e, const float* __restrict__ b1e,
    const float* __restrict__ W2e, const float* __restrict__ b2e,
    float* __restrict__ e_out,
    int n_edges)
{
    extern __shared__ char smem[];
    uint32_t* sA_hi  = (uint32_t*)(smem + E_SA_HI);
    uint32_t* sA_lo  = (uint32_t*)(smem + E_SA_LO);
    uint32_t* sW1_hi = (uint32_t*)(smem + E_SW1_HI);
    uint32_t* sW1_lo = (uint32_t*)(smem + E_SW1_LO);
    uint32_t* sH_hi  = (uint32_t*)(smem + E_SH_HI);
    uint32_t* sH_lo  = (uint32_t*)(smem + E_SH_LO);
    uint32_t* sW2_hi = (uint32_t*)(smem + E_SW2_HI);
    uint32_t* sW2_lo = (uint32_t*)(smem + E_SW2_LO);
    float* bias1 = (float*)(smem + E_BIAS1);
    float* bias2 = (float*)(smem + E_BIAS2);
    int*   sr    = (int*)(smem + E_SR);
    int*   sc    = (int*)(smem + E_SC);

    int tid = threadIdx.x;

    for (int i = tid; i < 64 * 64; i += 256) {
        int k = i >> 6, n = i & 63;
        float w = W1e[(128 + k) * 64 + n];
        __nv_bfloat16 wh = __float2bfloat16_rn(w);
        __nv_bfloat16 wl = __float2bfloat16_rn(w - __bfloat162float(wh));
        ((__nv_bfloat16*)sW1_hi)[n * 72 + k] = wh;
        ((__nv_bfloat16*)sW1_lo)[n * 72 + k] = wl;
    }
    for (int i = tid; i < 64 * 64; i += 256) {
        int k = i >> 6, n = i & 63;
        float w = W2e[i];
        __nv_bfloat16 wh = __float2bfloat16_rn(w);
        __nv_bfloat16 wl = __float2bfloat16_rn(w - __bfloat162float(wh));
        ((__nv_bfloat16*)sW2_hi)[n * 72 + k] = wh;
        ((__nv_bfloat16*)sW2_lo)[n * 72 + k] = wl;
    }
    if (tid < 64) {
        bias1[tid] = b1e[tid];
        bias2[tid] = b2e[tid];
    }
    __syncthreads();

    const int warp = tid >> 5, lane = tid & 31;
    const int g = lane >> 2, t = lane & 3;
    const int wr = warp << 4;
    const int row = tid >> 1, half = tid & 1;

    int nTiles = (n_edges + 127) >> 7;

    for (int tile = blockIdx.x; tile < nTiles; tile += gridDim.x) {
        int ebase = tile << 7;

        // ---- gather edge_attr + indices (warp-private rows) ----
        {
            int er = ebase + row;
            bool v = er < n_edges;
            int eid = v ? er : (n_edges - 1);
            if (half == 0) {
                int2 rc = ((const int2*)edge_index)[eid];
                sr[row] = rc.x;
                sc[row] = rc.y;
                if (v) atomicAdd(&g_deg[rc.y], 1.0f);
            }
            const float4* fe = (const float4*)(edge_attr + (size_t)eid * 64) + half * 8;
            #pragma unroll
            for (int cc = 0; cc < 4; cc++) {
                float4 va = fe[cc * 2], vb = fe[cc * 2 + 1];
                uint4 uh, ul;
                split2(va.x, va.y, uh.x, ul.x);
                split2(va.z, va.w, uh.y, ul.y);
                split2(vb.x, vb.y, uh.z, ul.z);
                split2(vb.z, vb.w, uh.w, ul.w);
                int col = half * 32 + cc * 8;
                int widx = row * 36 + (col >> 1);
                *(uint4*)(sA_hi + widx) = uh;
                *(uint4*)(sA_lo + widx) = ul;
            }
        }
        __syncwarp();

        // ---- GEMM1: edge_attr @ W1c, K=64, pass-split for dep-free mma chains ----
        float d[8][4];
        #pragma unroll
        for (int i = 0; i < 8; i++)
            #pragma unroll
            for (int j = 0; j < 4; j++) d[i][j] = 0.0f;

        #pragma unroll 1
        for (int kt = 0; kt < 4; kt++) {
            int ab = (wr + g) * 36 + kt * 8 + t;
            uint32_t ah[4], al[4];
            ah[0] = sA_hi[ab];       ah[1] = sA_hi[ab + 288];
            ah[2] = sA_hi[ab + 4];   ah[3] = sA_hi[ab + 292];
            al[0] = sA_lo[ab];       al[1] = sA_lo[ab + 288];
            al[2] = sA_lo[ab + 4];   al[3] = sA_lo[ab + 292];
            int bbase = g * 36 + kt * 8 + t;
            #pragma unroll
            for (int nt = 0; nt < 8; nt++) {
                int bb = bbase + nt * 288;
                uint32_t b2[2] = { sW1_hi[bb], sW1_hi[bb + 4] };
                mma16816(d[nt], ah, b2);
            }
            #pragma unroll
            for (int nt = 0; nt < 8; nt++) {
                int bb = bbase + nt * 288;
                uint32_t b2[2] = { sW1_lo[bb], sW1_lo[bb + 4] };
                mma16816(d[nt], ah, b2);
            }
            #pragma unroll
            for (int nt = 0; nt < 8; nt++) {
                int bb = bbase + nt * 288;
                uint32_t b2[2] = { sW1_hi[bb], sW1_hi[bb + 4] };
                mma16816(d[nt], al, b2);
            }
        }

        // ---- epilogue 1: h = relu(d + P[r][c] + P[c][64+c] + b1) -> sH ----
        {
            int rr0 = sr[wr + g],     cc0 = sc[wr + g];
            int rr1 = sr[wr + 8 + g], cc1 = sc[wr + 8 + g];
            const float* P0r = g_P + (size_t)rr0 * 128;
            const float* P0c = g_P + (size_t)cc0 * 128 + 64;
            const float* P1r = g_P + (size_t)rr1 * 128;
            const float* P1c = g_P + (size_t)cc1 * 128 + 64;
            #pragma unroll
            for (int nt = 0; nt < 8; nt++) {
                int c0 = nt * 8 + 2 * t;
                float2 pa = *(const float2*)(P0r + c0);
                float2 pb = *(const float2*)(P0c + c0);
                float2 pc_ = *(const float2*)(P1r + c0);
                float2 pd = *(const float2*)(P1c + c0);
                float bb0 = bias1[c0], bb1 = bias1[c0 + 1];
                float h0 = fmaxf(d[nt][0] + pa.x + pb.x + bb0, 0.f);
                float h1 = fmaxf(d[nt][1] + pa.y + pb.y + bb1, 0.f);
                float h2 = fmaxf(d[nt][2] + pc_.x + pd.x + bb0, 0.f);
                float h3 = fmaxf(d[nt][3] + pc_.y + pd.y + bb1, 0.f);
                uint32_t uh, ul;
                int w0 = (wr + g) * 36 + nt * 4 + t;
                split2(h0, h1, uh, ul);
                sH_hi[w0] = uh; sH_lo[w0] = ul;
                split2(h2, h3, uh, ul);
                sH_hi[w0 + 288] = uh; sH_lo[w0 + 288] = ul;
            }
        }
        __syncwarp();

        // ---- GEMM2: K=64, pass-split ----
        float d2[8][4];
        #pragma unroll
        for (int i = 0; i < 8; i++)
            #pragma unroll
            for (int j = 0; j < 4; j++) d2[i][j] = 0.0f;

        #pragma unroll 1
        for (int kt = 0; kt < 4; kt++) {
            int ab = (wr + g) * 36 + kt * 8 + t;
            uint32_t ah[4], al[4];
            ah[0] = sH_hi[ab];       ah[1] = sH_hi[ab + 288];
            ah[2] = sH_hi[ab + 4];   ah[3] = sH_hi[ab + 292];
            al[0] = sH_lo[ab];       al[1] = sH_lo[ab + 288];
            al[2] = sH_lo[ab + 4];   al[3] = sH_lo[ab + 292];
            int bbase = g * 36 + kt * 8 + t;
            #pragma unroll
            for (int nt = 0; nt < 8; nt++) {
                int bb = bbase + nt * 288;
                uint32_t b2[2] = { sW2_hi[bb], sW2_hi[bb + 4] };
                mma16816(d2[nt], ah, b2);
            }
            #pragma unroll
            for (int nt = 0; nt < 8; nt++) {
                int bb = bbase + nt * 288;
                uint32_t b2[2] = { sW2_lo[bb], sW2_lo[bb + 4] };
                mma16816(d2[nt], ah, b2);
            }
            #pragma unroll
            for (int nt = 0; nt < 8; nt++) {
                int bb = bbase + nt * 288;
                uint32_t b2[2] = { sW2_hi[bb], sW2_hi[bb + 4] };
                mma16816(d2[nt], al, b2);
            }
        }

        // ---- epilogue 2: stage e rows WARP-CONTAINED over this warp's dead sH
        //      rows (same 36-word row stride: cols 0-31 -> sH_hi[row][0:32],
        //      cols 32-63 -> sH_lo[row][0:32]), then v4 stores/reds ----
        {
            float* sE_hi = (float*)(smem + E_SH_HI);   // [128][36] words
            float* sE_lo = (float*)(smem + E_SH_LO);   // [128][36] words
            #pragma unroll
            for (int nt = 0; nt < 8; nt++) {
                int c0 = nt * 8 + 2 * t;
                float bb0 = bias2[c0], bb1 = bias2[c0 + 1];
                float2 v0 = make_float2(d2[nt][0] + bb0, d2[nt][1] + bb1);
                float2 v1 = make_float2(d2[nt][2] + bb0, d2[nt][3] + bb1);
                if (c0 < 32) {
                    *(float2*)(sE_hi + (wr + g) * 36 + c0) = v0;
                    *(float2*)(sE_hi + (wr + 8 + g) * 36 + c0) = v1;
                } else {
                    *(float2*)(sE_lo + (wr + g) * 36 + (c0 - 32)) = v0;
                    *(float2*)(sE_lo + (wr + 8 + g) * 36 + (c0 - 32)) = v1;
                }
            }
            __syncwarp();
            int rl = lane >> 1;            // 0..15 within warp tile
            int hf = lane & 1;             // 0: cols 0-31, 1: cols 32-63
            int r = wr + rl;
            int er = ebase + r;
            bool v = er < n_edges;
            int cd = sc[r];
            const float* src = (hf ? sE_lo : sE_hi) + r * 36;
            float* eo = e_out + (size_t)er * 64 + hf * 32;
            float* ag = g_agg + (size_t)cd * 64 + hf * 32;
            if (v) {
                #pragma unroll
                for (int q = 0; q < 8; q++) {
                    float4 vv = *(const float4*)(src + q * 4);
                    *(float4*)(eo + q * 4) = vv;
                    red_add4(ag + q * 4, vv);
                }
            }
        }
        __syncwarp();
    }
}

// ======================= node kernel =======================
#define N_SA_HI   0u
#define N_SA_LO   34816u
#define N_SW1_HI  69632u
#define N_SW1_LO  87040u
#define N_SH_HI   104448u
#define N_SH_LO   122880u
#define N_SW2_HI  141312u
#define N_SW2_LO  150528u
#define N_BIAS1   159744u
#define N_BIAS2   160000u
#define N_SMEM    160256u

__global__ void __launch_bounds__(256, 1) node_kernel(
    const float* __restrict__ feats,
    const float* __restrict__ W1n, const float* __restrict__ b1n,
    const float* __restrict__ W2n, const float* __restrict__ b2n,
    float* __restrict__ feats_out,
    int n_nodes)
{
    extern __shared__ char smem[];
    uint32_t* sA_hi  = (uint32_t*)(smem + N_SA_HI);
    uint32_t* sA_lo  = (uint32_t*)(smem + N_SA_LO);
    uint32_t* sW1_hi = (uint32_t*)(smem + N_SW1_HI);
    uint32_t* sW1_lo = (uint32_t*)(smem + N_SW1_LO);
    uint32_t* sH_hi  = (uint32_t*)(smem + N_SH_HI);
    uint32_t* sH_lo  = (uint32_t*)(smem + N_SH_LO);
    uint32_t* sW2_hi = (uint32_t*)(smem + N_SW2_HI);
    uint32_t* sW2_lo = (uint32_t*)(smem + N_SW2_LO);
    float* bias1 = (float*)(smem + N_BIAS1);
    float* bias2 = (float*)(smem + N_BIAS2);

    int tid = threadIdx.x;

    for (int i = tid; i < 128 * 64; i += 256) {
        int k = i >> 6, n = i & 63;
        float w = W1n[i];
        __nv_bfloat16 wh = __float2bfloat16_rn(w);
        __nv_bfloat16 wl = __float2bfloat16_rn(w - __bfloat162float(wh));
        ((__nv_bfloat16*)sW1_hi)[n * 136 + k] = wh;
        ((__nv_bfloat16*)sW1_lo)[n * 136 + k] = wl;
    }
    for (int i = tid; i < 64 * 64; i += 256) {
        int k = i >> 6, n = i & 63;
        float w = W2n[i];
        __nv_bfloat16 wh = __float2bfloat16_rn(w);
        __nv_bfloat16 wl = __float2bfloat16_rn(w - __bfloat162float(wh));
        ((__nv_bfloat16*)sW2_hi)[n * 72 + k] = wh;
        ((__nv_bfloat16*)sW2_lo)[n * 72 + k] = wl;
    }
    if (tid < 64) {
        bias1[tid] = b1n[tid];
        bias2[tid] = b2n[tid];
    }
    __syncthreads();

    const int warp = tid >> 5, lane = tid & 31;
    const int g = lane >> 2, t = lane & 3;
    const int wr = warp << 4;
    const int row = tid >> 1, half = tid & 1;

    int nTiles = (n_nodes + 127) >> 7;

    for (int tile = blockIdx.x; tile < nTiles; tile += gridDim.x) {
        int nbase = tile << 7;

        {
            int nr = nbase + row;
            int nid = nr < n_nodes ? nr : (n_nodes - 1);
            const float4* src;
            float scale;
            if (half == 0) {
                src = (const float4*)(feats + (size_t)nid * 64);
                scale = 1.0f;
            } else {
                src = (const float4*)(g_agg + (size_t)nid * 64);
                scale = 1.0f / fmaxf(g_deg[nid], 1.0f);
            }
            #pragma unroll
            for (int cc = 0; cc < 8; cc++) {
                float4 va = src[cc * 2], vb = src[cc * 2 + 1];
                va.x *= scale; va.y *= scale; va.z *= scale; va.w *= scale;
                vb.x *= scale; vb.y *= scale; vb.z *= scale; vb.w *= scale;
                uint4 uh, ul;
                split2(va.x, va.y, uh.x, ul.x);
                split2(va.z, va.w, uh.y, ul.y);
                split2(vb.x, vb.y, uh.z, ul.z);
                split2(vb.z, vb.w, uh.w, ul.w);
                int col = half * 64 + cc * 8;
                int widx = row * 68 + (col >> 1);
                *(uint4*)(sA_hi + widx) = uh;
                *(uint4*)(sA_lo + widx) = ul;
            }
        }
        __syncwarp();

        float d[8][4];
        #pragma unroll
        for (int i = 0; i < 8; i++)
            #pragma unroll
            for (int j = 0; j < 4; j++) d[i][j] = 0.0f;

        #pragma unroll 1
        for (int kt = 0; kt < 8; kt++) {
            int ab = (wr + g) * 68 + kt * 8 + t;
            uint32_t ah[4], al[4];
            ah[0] = sA_hi[ab];       ah[1] = sA_hi[ab + 544];
            ah[2] = sA_hi[ab + 4];   ah[3] = sA_hi[ab + 548];
            al[0] = sA_lo[ab];       al[1] = sA_lo[ab + 544];
            al[2] = sA_lo[ab + 4];   al[3] = sA_lo[ab + 548];
            int bbase = g * 68 + kt * 8 + t;
            #pragma unroll
            for (int nt = 0; nt < 8; nt++) {
                int bb = bbase + nt * 544;
                uint32_t b2[2] = { sW1_hi[bb], sW1_hi[bb + 4] };
                mma16816(d[nt], ah, b2);
            }
            #pragma unroll
            for (int nt = 0; nt < 8; nt++) {
                int bb = bbase + nt * 544;
                uint32_t b2[2] = { sW1_lo[bb], sW1_lo[bb + 4] };
                mma16816(d[nt], ah, b2);
            }
            #pragma unroll
            for (int nt = 0; nt < 8; nt++) {
                int bb = bbase + nt * 544;
                uint32_t b2[2] = { sW1_hi[bb], sW1_hi[bb + 4] };
                mma16816(d[nt], al, b2);
            }
        }

        #pragma unroll
        for (int nt = 0; nt < 8; nt++) {
            int c0 = nt * 8 + 2 * t;
            float bb0 = bias1[c0], bb1 = bias1[c0 + 1];
            float h0 = fmaxf(d[nt][0] + bb0, 0.f), h1 = fmaxf(d[nt][1] + bb1, 0.f);
            float h2 = fmaxf(d[nt][2] + bb0, 0.f), h3 = fmaxf(d[nt][3] + bb1, 0.f);
            uint32_t uh, ul;
            int w0 = (wr + g) * 36 + nt * 4 + t;
            split2(h0, h1, uh, ul);
            sH_hi[w0] = uh; sH_lo[w0] = ul;
            split2(h2, h3, uh, ul);
            sH_hi[w0 + 288] = uh; sH_lo[w0 + 288] = ul;
        }
        __syncwarp();

        float d2[8][4];
        #pragma unroll
        for (int i = 0; i < 8; i++)
            #pragma unroll
            for (int j = 0; j < 4; j++) d2[i][j] = 0.0f;

        #pragma unroll 1
        for (int kt = 0; kt < 4; kt++) {
            int ab = (wr + g) * 36 + kt * 8 + t;
            uint32_t ah[4], al[4];
            ah[0] = sH_hi[ab];       ah[1] = sH_hi[ab + 288];
            ah[2] = sH_hi[ab + 4];   ah[3] = sH_hi[ab + 292];
            al[0] = sH_lo[ab];       al[1] = sH_lo[ab + 288];
            al[2] = sH_lo[ab + 4];   al[3] = sH_lo[ab + 292];
            int bbase = g * 36 + kt * 8 + t;
            #pragma unroll
            for (int nt = 0; nt < 8; nt++) {
                int bb = bbase + nt * 288;
                uint32_t b2[2] = { sW2_hi[bb], sW2_hi[bb + 4] };
                mma16816(d2[nt], ah, b2);
            }
            #pragma unroll
            for (int nt = 0; nt < 8; nt++) {
                int bb = bbase + nt * 288;
                uint32_t b2[2] = { sW2_lo[bb], sW2_lo[bb + 4] };
                mma16816(d2[nt], ah, b2);
            }
            #pragma unroll
            for (int nt = 0; nt < 8; nt++) {
                int bb = bbase + nt * 288;
                uint32_t b2[2] = { sW2_hi[bb], sW2_hi[bb + 4] };
                mma16816(d2[nt], al, b2);
            }
        }

        {
            int r0 = nbase + wr + g, r1 = r0 + 8;
            bool v0 = r0 < n_nodes, v1 = r1 < n_nodes;
            #pragma unroll
            for (int nt = 0; nt < 8; nt++) {
                int c0 = nt * 8 + 2 * t;
                float bb0 = bias2[c0], bb1 = bias2[c0 + 1];
                if (v0)
                    *(float2*)(feats_out + (size_t)r0 * 64 + c0) =
                        make_float2(d2[nt][0] + bb0, d2[nt][1] + bb1);
                if (v1)
                    *(float2*)(feats_out + (size_t)r1 * 64 + c0) =
                        make_float2(d2[nt][2] + bb0, d2[nt][3] + bb1);
            }
        }
        __syncwarp();
    }
}

// ======================= launch =======================
extern "C" void kernel_launch(void* const* d_in, const int* in_sizes, int n_in,
                              void* d_out, int out_size) {
    const float* feats      = (const float*)d_in[0];
    const int*   edge_index = (const int*)d_in[1];
    const float* edge_attr  = (const float*)d_in[2];
    const float* W1e        = (const float*)d_in[3];
    const float* b1e        = (const float*)d_in[4];
    const float* W2e        = (const float*)d_in[5];
    const float* b2e        = (const float*)d_in[6];
    const float* W1n        = (const float*)d_in[7];
    const float* b1n        = (const float*)d_in[8];
    const float* W2n        = (const float*)d_in[9];
    const float* b2n        = (const float*)d_in[10];

    int n_nodes = in_sizes[0] / 64;
    int n_edges = in_sizes[2] / 64;

    float* out       = (float*)d_out;
    float* feats_out = out;                          // [n_nodes, 64]
    float* e_out     = out + (size_t)n_nodes * 64;   // [n_edges, 64]

    cudaFuncSetAttribute(pnode_kernel, cudaFuncAttributeMaxDynamicSharedMemorySize, P_SMEM);
    cudaFuncSetAttribute(edge_kernel, cudaFuncAttributeMaxDynamicSharedMemorySize, E_SMEM);
    cudaFuncSetAttribute(node_kernel, cudaFuncAttributeMaxDynamicSharedMemorySize, N_SMEM);

    zero_kernel<<<1024, 256>>>(n_nodes);
    pnode_kernel<<<296, 256, P_SMEM>>>(feats, W1e, n_nodes);
    edge_kernel<<<296, 256, E_SMEM>>>(feats, edge_index, edge_attr,
                                      W1e, b1e, W2e, b2e, e_out, n_edges);
    node_kernel<<<148, 256, N_SMEM>>>(feats, W1n, b1n, W2n, b2n,
                                      feats_out, n_nodes);
}

// round 9
// speedup vs baseline: 1.1982x; 1.1982x over previous
#include <cuda_runtime.h>
#include <cuda_bf16.h>
#include <cstdint>

#define MAX_NODES 50000

__device__ float g_agg[MAX_NODES * 64];
__device__ float g_deg[MAX_NODES];
__device__ float g_P[MAX_NODES * 128];   // P[v] = feats[v] @ [W1e[0:64]||W1e[64:128]]

// ---------------- helpers ----------------
__device__ __forceinline__ void mma16816(float d[4], const uint32_t a[4],
                                         const uint32_t b[2]) {
    asm("mma.sync.aligned.m16n8k16.row.col.f32.bf16.bf16.f32 "
        "{%0,%1,%2,%3}, {%4,%5,%6,%7}, {%8,%9}, {%0,%1,%2,%3};"
        : "+f"(d[0]), "+f"(d[1]), "+f"(d[2]), "+f"(d[3])
        : "r"(a[0]), "r"(a[1]), "r"(a[2]), "r"(a[3]), "r"(b[0]), "r"(b[1]));
}

__device__ __forceinline__ void split2(float x0, float x1,
                                       uint32_t& uh, uint32_t& ul) {
    __nv_bfloat162 bh = __floats2bfloat162_rn(x0, x1);
    float2 back = __bfloat1622float2(bh);
    __nv_bfloat162 bl = __floats2bfloat162_rn(x0 - back.x, x1 - back.y);
    uh = *(uint32_t*)&bh;
    ul = *(uint32_t*)&bl;
}

__device__ __forceinline__ void red_add2(float* addr, float a, float b) {
    asm volatile("red.global.add.v2.f32 [%0], {%1, %2};"
                 :: "l"(addr), "f"(a), "f"(b) : "memory");
}

// ---------------- kernel 0: zero scratch ----------------
__global__ void zero_kernel(int n_nodes) {
    int i = blockIdx.x * blockDim.x + threadIdx.x;
    int stride = gridDim.x * blockDim.x;
    int tot = n_nodes * 64;
    for (int k = i; k < tot; k += stride) g_agg[k] = 0.0f;
    for (int k = i; k < n_nodes; k += stride) g_deg[k] = 0.0f;
}

// ======================= P precompute kernel =======================
#define P_SA_HI 0u
#define P_SA_LO 18432u
#define P_SW_HI 36864u
#define P_SW_LO 55296u
#define P_SMEM  73728u

__global__ void __launch_bounds__(256, 2) pnode_kernel(
    const float* __restrict__ feats,
    const float* __restrict__ W1e,
    int n_nodes)
{
    extern __shared__ char smem[];
    uint32_t* sA_hi = (uint32_t*)(smem + P_SA_HI);
    uint32_t* sA_lo = (uint32_t*)(smem + P_SA_LO);
    uint32_t* sW_hi = (uint32_t*)(smem + P_SW_HI);
    uint32_t* sW_lo = (uint32_t*)(smem + P_SW_LO);

    int tid = threadIdx.x;
    for (int i = tid; i < 128 * 64; i += 256) {
        int n = i & 127, k = i >> 7;
        float w = (n < 64) ? W1e[k * 64 + n] : W1e[(64 + k) * 64 + (n - 64)];
        __nv_bfloat16 wh = __float2bfloat16_rn(w);
        __nv_bfloat16 wl = __float2bfloat16_rn(w - __bfloat162float(wh));
        ((__nv_bfloat16*)sW_hi)[n * 72 + k] = wh;
        ((__nv_bfloat16*)sW_lo)[n * 72 + k] = wl;
    }
    __syncthreads();

    const int warp = tid >> 5, lane = tid & 31;
    const int g = lane >> 2, t = lane & 3;
    const int wr = warp << 4;
    const int row = tid >> 1, half = tid & 1;

    int nTiles = (n_nodes + 127) >> 7;

    for (int tile = blockIdx.x; tile < nTiles; tile += gridDim.x) {
        int nbase = tile << 7;
        {
            int nr = nbase + row;
            int nid = nr < n_nodes ? nr : (n_nodes - 1);
            const float4* src = (const float4*)(feats + (size_t)nid * 64) + half * 8;
            #pragma unroll
            for (int cc = 0; cc < 4; cc++) {
                float4 va = src[cc * 2], vb = src[cc * 2 + 1];
                uint4 uh, ul;
                split2(va.x, va.y, uh.x, ul.x);
                split2(va.z, va.w, uh.y, ul.y);
                split2(vb.x, vb.y, uh.z, ul.z);
                split2(vb.z, vb.w, uh.w, ul.w);
                int col = half * 32 + cc * 8;
                int widx = row * 36 + (col >> 1);
                *(uint4*)(sA_hi + widx) = uh;
                *(uint4*)(sA_lo + widx) = ul;
            }
        }
        __syncwarp();

        float d[16][4];
        #pragma unroll
        for (int i = 0; i < 16; i++)
            #pragma unroll
            for (int j = 0; j < 4; j++) d[i][j] = 0.0f;

        #pragma unroll 1
        for (int kt = 0; kt < 4; kt++) {
            int ab = (wr + g) * 36 + kt * 8 + t;
            uint32_t ah[4], al[4];
            ah[0] = sA_hi[ab];       ah[1] = sA_hi[ab + 288];
            ah[2] = sA_hi[ab + 4];   ah[3] = sA_hi[ab + 292];
            al[0] = sA_lo[ab];       al[1] = sA_lo[ab + 288];
            al[2] = sA_lo[ab + 4];   al[3] = sA_lo[ab + 292];
            #pragma unroll
            for (int nt = 0; nt < 16; nt++) {
                int bb = (nt * 8 + g) * 36 + kt * 8 + t;
                uint32_t bh[2] = { sW_hi[bb], sW_hi[bb + 4] };
                uint32_t bl[2] = { sW_lo[bb], sW_lo[bb + 4] };
                mma16816(d[nt], ah, bh);
                mma16816(d[nt], ah, bl);
                mma16816(d[nt], al, bh);
            }
        }

        {
            int r0 = nbase + wr + g, r1 = r0 + 8;
            bool v0 = r0 < n_nodes, v1 = r1 < n_nodes;
            #pragma unroll
            for (int nt = 0; nt < 16; nt++) {
                int c0 = nt * 8 + 2 * t;
                if (v0) *(float2*)(g_P + (size_t)r0 * 128 + c0) =
                            make_float2(d[nt][0], d[nt][1]);
                if (v1) *(float2*)(g_P + (size_t)r1 * 128 + c0) =
                            make_float2(d[nt][2], d[nt][3]);
            }
        }
        __syncwarp();
    }
}

// ======================= edge kernel =======================
// sH aliases sA (A fully consumed by GEMM1 before epilogue-1 writes H;
// both [128][36] words, warp-private rows) -> 75.3KB/block -> 3 blocks/SM
#define E_SA_HI   0u
#define E_SA_LO   18432u
#define E_SW1_HI  36864u
#define E_SW1_LO  46080u
#define E_SW2_HI  55296u
#define E_SW2_LO  64512u
#define E_BIAS1   73728u
#define E_BIAS2   73984u
#define E_SR      74240u
#define E_SC      74752u
#define E_SMEM    75264u

__global__ void __launch_bounds__(256, 3) edge_kernel(
    const float* __restrict__ feats,
    const int* __restrict__ edge_index,
    const float* __restrict__ edge_attr,
    const float* __restrict__ W1e, const float* __restrict__ b1e,
    const float* __restrict__ W2e, const float* __restrict__ b2e,
    float* __restrict__ e_out,
    int n_edges)
{
    extern __shared__ char smem[];
    uint32_t* sA_hi  = (uint32_t*)(smem + E_SA_HI);
    uint32_t* sA_lo  = (uint32_t*)(smem + E_SA_LO);
    uint32_t* sW1_hi = (uint32_t*)(smem + E_SW1_HI);
    uint32_t* sW1_lo = (uint32_t*)(smem + E_SW1_LO);
    uint32_t* sH_hi  = sA_hi;   // alias: H overwrites A (warp-private rows)
    uint32_t* sH_lo  = sA_lo;
    uint32_t* sW2_hi = (uint32_t*)(smem + E_SW2_HI);
    uint32_t* sW2_lo = (uint32_t*)(smem + E_SW2_LO);
    float* bias1 = (float*)(smem + E_BIAS1);
    float* bias2 = (float*)(smem + E_BIAS2);
    int*   sr    = (int*)(smem + E_SR);
    int*   sc    = (int*)(smem + E_SC);

    int tid = threadIdx.x;

    for (int i = tid; i < 64 * 64; i += 256) {
        int k = i >> 6, n = i & 63;
        float w = W1e[(128 + k) * 64 + n];
        __nv_bfloat16 wh = __float2bfloat16_rn(w);
        __nv_bfloat16 wl = __float2bfloat16_rn(w - __bfloat162float(wh));
        ((__nv_bfloat16*)sW1_hi)[n * 72 + k] = wh;
        ((__nv_bfloat16*)sW1_lo)[n * 72 + k] = wl;
    }
    for (int i = tid; i < 64 * 64; i += 256) {
        int k = i >> 6, n = i & 63;
        float w = W2e[i];
        __nv_bfloat16 wh = __float2bfloat16_rn(w);
        __nv_bfloat16 wl = __float2bfloat16_rn(w - __bfloat162float(wh));
        ((__nv_bfloat16*)sW2_hi)[n * 72 + k] = wh;
        ((__nv_bfloat16*)sW2_lo)[n * 72 + k] = wl;
    }
    if (tid < 64) {
        bias1[tid] = b1e[tid];
        bias2[tid] = b2e[tid];
    }
    __syncthreads();

    const int warp = tid >> 5, lane = tid & 31;
    const int g = lane >> 2, t = lane & 3;
    const int wr = warp << 4;
    const int row = tid >> 1, half = tid & 1;

    int nTiles = (n_edges + 127) >> 7;

    for (int tile = blockIdx.x; tile < nTiles; tile += gridDim.x) {
        int ebase = tile << 7;

        // ---- gather edge_attr + indices (warp-private rows) ----
        {
            int er = ebase + row;
            bool v = er < n_edges;
            int eid = v ? er : (n_edges - 1);
            if (half == 0) {
                int2 rc = ((const int2*)edge_index)[eid];
                sr[row] = rc.x;
                sc[row] = rc.y;
                if (v) atomicAdd(&g_deg[rc.y], 1.0f);
            }
            const float4* fe = (const float4*)(edge_attr + (size_t)eid * 64) + half * 8;
            #pragma unroll
            for (int cc = 0; cc < 4; cc++) {
                float4 va = fe[cc * 2], vb = fe[cc * 2 + 1];
                uint4 uh, ul;
                split2(va.x, va.y, uh.x, ul.x);
                split2(va.z, va.w, uh.y, ul.y);
                split2(vb.x, vb.y, uh.z, ul.z);
                split2(vb.z, vb.w, uh.w, ul.w);
                int col = half * 32 + cc * 8;
                int widx = row * 36 + (col >> 1);
                *(uint4*)(sA_hi + widx) = uh;
                *(uint4*)(sA_lo + widx) = ul;
            }
        }
        __syncwarp();

        // ---- GEMM1: edge_attr @ W1c, K=64 ----
        float d[8][4];
        #pragma unroll
        for (int i = 0; i < 8; i++)
            #pragma unroll
            for (int j = 0; j < 4; j++) d[i][j] = 0.0f;

        #pragma unroll 1
        for (int kt = 0; kt < 4; kt++) {
            int ab = (wr + g) * 36 + kt * 8 + t;
            uint32_t ah[4], al[4];
            ah[0] = sA_hi[ab];       ah[1] = sA_hi[ab + 288];
            ah[2] = sA_hi[ab + 4];   ah[3] = sA_hi[ab + 292];
            al[0] = sA_lo[ab];       al[1] = sA_lo[ab + 288];
            al[2] = sA_lo[ab + 4];   al[3] = sA_lo[ab + 292];
            #pragma unroll
            for (int nt = 0; nt < 8; nt++) {
                int bb = (nt * 8 + g) * 36 + kt * 8 + t;
                uint32_t bh[2] = { sW1_hi[bb], sW1_hi[bb + 4] };
                uint32_t bl[2] = { sW1_lo[bb], sW1_lo[bb + 4] };
                mma16816(d[nt], ah, bh);
                mma16816(d[nt], ah, bl);
                mma16816(d[nt], al, bh);
            }
        }

        // ---- epilogue 1: h = relu(d + P[r][c] + P[c][64+c] + b1) -> sH(=sA) ----
        {
            int rr0 = sr[wr + g],     cc0 = sc[wr + g];
            int rr1 = sr[wr + 8 + g], cc1 = sc[wr + 8 + g];
            const float* P0r = g_P + (size_t)rr0 * 128;
            const float* P0c = g_P + (size_t)cc0 * 128 + 64;
            const float* P1r = g_P + (size_t)rr1 * 128;
            const float* P1c = g_P + (size_t)cc1 * 128 + 64;
            #pragma unroll
            for (int nt = 0; nt < 8; nt++) {
                int c0 = nt * 8 + 2 * t;
                float2 pa = *(const float2*)(P0r + c0);
                float2 pb = *(const float2*)(P0c + c0);
                float2 pc_ = *(const float2*)(P1r + c0);
                float2 pd = *(const float2*)(P1c + c0);
                float bb0 = bias1[c0], bb1 = bias1[c0 + 1];
                float h0 = fmaxf(d[nt][0] + pa.x + pb.x + bb0, 0.f);
                float h1 = fmaxf(d[nt][1] + pa.y + pb.y + bb1, 0.f);
                float h2 = fmaxf(d[nt][2] + pc_.x + pd.x + bb0, 0.f);
                float h3 = fmaxf(d[nt][3] + pc_.y + pd.y + bb1, 0.f);
                uint32_t uh, ul;
                int w0 = (wr + g) * 36 + nt * 4 + t;
                split2(h0, h1, uh, ul);
                sH_hi[w0] = uh; sH_lo[w0] = ul;
                split2(h2, h3, uh, ul);
                sH_hi[w0 + 288] = uh; sH_lo[w0 + 288] = ul;
            }
        }
        __syncwarp();

        // ---- GEMM2: K=64 ----
        float d2[8][4];
        #pragma unroll
        for (int i = 0; i < 8; i++)
            #pragma unroll
            for (int j = 0; j < 4; j++) d2[i][j] = 0.0f;

        #pragma unroll 1
        for (int kt = 0; kt < 4; kt++) {
            int ab = (wr + g) * 36 + kt * 8 + t;
            uint32_t ah[4], al[4];
            ah[0] = sH_hi[ab];       ah[1] = sH_hi[ab + 288];
            ah[2] = sH_hi[ab + 4];   ah[3] = sH_hi[ab + 292];
            al[0] = sH_lo[ab];       al[1] = sH_lo[ab + 288];
            al[2] = sH_lo[ab + 4];   al[3] = sH_lo[ab + 292];
            #pragma unroll
            for (int nt = 0; nt < 8; nt++) {
                int bb = (nt * 8 + g) * 36 + kt * 8 + t;
                uint32_t bh[2] = { sW2_hi[bb], sW2_hi[bb + 4] };
                uint32_t bl[2] = { sW2_lo[bb], sW2_lo[bb + 4] };
                mma16816(d2[nt], ah, bh);
                mma16816(d2[nt], ah, bl);
                mma16816(d2[nt], al, bh);
            }
        }

        // ---- epilogue 2: e = D2 + b2 -> e_out + vector red to g_agg ----
        {
            int r0 = ebase + wr + g, r1 = r0 + 8;
            bool v0 = r0 < n_edges, v1 = r1 < n_edges;
            int ca = sc[wr + g], cb = sc[wr + 8 + g];
            #pragma unroll
            for (int nt = 0; nt < 8; nt++) {
                int c0 = nt * 8 + 2 * t;
                float bb0 = bias2[c0], bb1 = bias2[c0 + 1];
                float e0 = d2[nt][0] + bb0, e1 = d2[nt][1] + bb1;
                float e2 = d2[nt][2] + bb0, e3 = d2[nt][3] + bb1;
                if (v0) {
                    *(float2*)(e_out + (size_t)r0 * 64 + c0) = make_float2(e0, e1);
                    red_add2(g_agg + (size_t)ca * 64 + c0, e0, e1);
                }
                if (v1) {
                    *(float2*)(e_out + (size_t)r1 * 64 + c0) = make_float2(e2, e3);
                    red_add2(g_agg + (size_t)cb * 64 + c0, e2, e3);
                }
            }
        }
        __syncwarp();
    }
}

// ======================= node kernel =======================
#define N_SA_HI   0u
#define N_SA_LO   34816u
#define N_SW1_HI  69632u
#define N_SW1_LO  87040u
#define N_SH_HI   104448u
#define N_SH_LO   122880u
#define N_SW2_HI  141312u
#define N_SW2_LO  150528u
#define N_BIAS1   159744u
#define N_BIAS2   160000u
#define N_SMEM    160256u

__global__ void __launch_bounds__(256, 1) node_kernel(
    const float* __restrict__ feats,
    const float* __restrict__ W1n, const float* __restrict__ b1n,
    const float* __restrict__ W2n, const float* __restrict__ b2n,
    float* __restrict__ feats_out,
    int n_nodes)
{
    extern __shared__ char smem[];
    uint32_t* sA_hi  = (uint32_t*)(smem + N_SA_HI);
    uint32_t* sA_lo  = (uint32_t*)(smem + N_SA_LO);
    uint32_t* sW1_hi = (uint32_t*)(smem + N_SW1_HI);
    uint32_t* sW1_lo = (uint32_t*)(smem + N_SW1_LO);
    uint32_t* sH_hi  = (uint32_t*)(smem + N_SH_HI);
    uint32_t* sH_lo  = (uint32_t*)(smem + N_SH_LO);
    uint32_t* sW2_hi = (uint32_t*)(smem + N_SW2_HI);
    uint32_t* sW2_lo = (uint32_t*)(smem + N_SW2_LO);
    float* bias1 = (float*)(smem + N_BIAS1);
    float* bias2 = (float*)(smem + N_BIAS2);

    int tid = threadIdx.x;

    for (int i = tid; i < 128 * 64; i += 256) {
        int k = i >> 6, n = i & 63;
        float w = W1n[i];
        __nv_bfloat16 wh = __float2bfloat16_rn(w);
        __nv_bfloat16 wl = __float2bfloat16_rn(w - __bfloat162float(wh));
        ((__nv_bfloat16*)sW1_hi)[n * 136 + k] = wh;
        ((__nv_bfloat16*)sW1_lo)[n * 136 + k] = wl;
    }
    for (int i = tid; i < 64 * 64; i += 256) {
        int k = i >> 6, n = i & 63;
        float w = W2n[i];
        __nv_bfloat16 wh = __float2bfloat16_rn(w);
        __nv_bfloat16 wl = __float2bfloat16_rn(w - __bfloat162float(wh));
        ((__nv_bfloat16*)sW2_hi)[n * 72 + k] = wh;
        ((__nv_bfloat16*)sW2_lo)[n * 72 + k] = wl;
    }
    if (tid < 64) {
        bias1[tid] = b1n[tid];
        bias2[tid] = b2n[tid];
    }
    __syncthreads();

    const int warp = tid >> 5, lane = tid & 31;
    const int g = lane >> 2, t = lane & 3;
    const int wr = warp << 4;
    const int row = tid >> 1, half = tid & 1;

    int nTiles = (n_nodes + 127) >> 7;

    for (int tile = blockIdx.x; tile < nTiles; tile += gridDim.x) {
        int nbase = tile << 7;

        {
            int nr = nbase + row;
            int nid = nr < n_nodes ? nr : (n_nodes - 1);
            const float4* src;
            float scale;
            if (half == 0) {
                src = (const float4*)(feats + (size_t)nid * 64);
                scale = 1.0f;
            } else {
                src = (const float4*)(g_agg + (size_t)nid * 64);
                scale = 1.0f / fmaxf(g_deg[nid], 1.0f);
            }
            #pragma unroll
            for (int cc = 0; cc < 8; cc++) {
                float4 va = src[cc * 2], vb = src[cc * 2 + 1];
                va.x *= scale; va.y *= scale; va.z *= scale; va.w *= scale;
                vb.x *= scale; vb.y *= scale; vb.z *= scale; vb.w *= scale;
                uint4 uh, ul;
                split2(va.x, va.y, uh.x, ul.x);
                split2(va.z, va.w, uh.y, ul.y);
                split2(vb.x, vb.y, uh.z, ul.z);
                split2(vb.z, vb.w, uh.w, ul.w);
                int col = half * 64 + cc * 8;
                int widx = row * 68 + (col >> 1);
                *(uint4*)(sA_hi + widx) = uh;
                *(uint4*)(sA_lo + widx) = ul;
            }
        }
        __syncwarp();

        float d[8][4];
        #pragma unroll
        for (int i = 0; i < 8; i++)
            #pragma unroll
            for (int j = 0; j < 4; j++) d[i][j] = 0.0f;

        #pragma unroll 1
        for (int kt = 0; kt < 8; kt++) {
            int ab = (wr + g) * 68 + kt * 8 + t;
            uint32_t ah[4], al[4];
            ah[0] = sA_hi[ab];       ah[1] = sA_hi[ab + 544];
            ah[2] = sA_hi[ab + 4];   ah[3] = sA_hi[ab + 548];
            al[0] = sA_lo[ab];       al[1] = sA_lo[ab + 544];
            al[2] = sA_lo[ab + 4];   al[3] = sA_lo[ab + 548];
            #pragma unroll
            for (int nt = 0; nt < 8; nt++) {
                int bb = (nt * 8 + g) * 68 + kt * 8 + t;
                uint32_t bh[2] = { sW1_hi[bb], sW1_hi[bb + 4] };
                uint32_t bl[2] = { sW1_lo[bb], sW1_lo[bb + 4] };
                mma16816(d[nt], ah, bh);
                mma16816(d[nt], ah, bl);
                mma16816(d[nt], al, bh);
            }
        }

        #pragma unroll
        for (int nt = 0; nt < 8; nt++) {
            int c0 = nt * 8 + 2 * t;
            float bb0 = bias1[c0], bb1 = bias1[c0 + 1];
            float h0 = fmaxf(d[nt][0] + bb0, 0.f), h1 = fmaxf(d[nt][1] + bb1, 0.f);
            float h2 = fmaxf(d[nt][2] + bb0, 0.f), h3 = fmaxf(d[nt][3] + bb1, 0.f);
            uint32_t uh, ul;
            int w0 = (wr + g) * 36 + nt * 4 + t;
            split2(h0, h1, uh, ul);
            sH_hi[w0] = uh; sH_lo[w0] = ul;
            split2(h2, h3, uh, ul);
            sH_hi[w0 + 288] = uh; sH_lo[w0 + 288] = ul;
        }
        __syncwarp();

        float d2[8][4];
        #pragma unroll
        for (int i = 0; i < 8; i++)
            #pragma unroll
            for (int j = 0; j < 4; j++) d2[i][j] = 0.0f;

        #pragma unroll 1
        for (int kt = 0; kt < 4; kt++) {
            int ab = (wr + g) * 36 + kt * 8 + t;
            uint32_t ah[4], al[4];
            ah[0] = sH_hi[ab];       ah[1] = sH_hi[ab + 288];
            ah[2] = sH_hi[ab + 4];   ah[3] = sH_hi[ab + 292];
            al[0] = sH_lo[ab];       al[1] = sH_lo[ab + 288];
            al[2] = sH_lo[ab + 4];   al[3] = sH_lo[ab + 292];
            #pragma unroll
            for (int nt = 0; nt < 8; nt++) {
                int bb = (nt * 8 + g) * 36 + kt * 8 + t;
                uint32_t bh[2] = { sW2_hi[bb], sW2_hi[bb + 4] };
                uint32_t bl[2] = { sW2_lo[bb], sW2_lo[bb + 4] };
                mma16816(d2[nt], ah, bh);
                mma16816(d2[nt], ah, bl);
                mma16816(d2[nt], al, bh);
            }
        }

        {
            int r0 = nbase + wr + g, r1 = r0 + 8;
            bool v0 = r0 < n_nodes, v1 = r1 < n_nodes;
            #pragma unroll
            for (int nt = 0; nt < 8; nt++) {
                int c0 = nt * 8 + 2 * t;
                float bb0 = bias2[c0], bb1 = bias2[c0 + 1];
                if (v0)
                    *(float2*)(feats_out + (size_t)r0 * 64 + c0) =
                        make_float2(d2[nt][0] + bb0, d2[nt][1] + bb1);
                if (v1)
                    *(float2*)(feats_out + (size_t)r1 * 64 + c0) =
                        make_float2(d2[nt][2] + bb0, d2[nt][3] + bb1);
            }
        }
        __syncwarp();
    }
}

// ======================= launch =======================
extern "C" void kernel_launch(void* const* d_in, const int* in_sizes, int n_in,
                              void* d_out, int out_size) {
    const float* feats      = (const float*)d_in[0];
    const int*   edge_index = (const int*)d_in[1];
    const float* edge_attr  = (const float*)d_in[2];
    const float* W1e        = (const float*)d_in[3];
    const float* b1e        = (const float*)d_in[4];
    const float* W2e        = (const float*)d_in[5];
    const float* b2e        = (const float*)d_in[6];
    const float* W1n        = (const float*)d_in[7];
    const float* b1n        = (const float*)d_in[8];
    const float* W2n        = (const float*)d_in[9];
    const float* b2n        = (const float*)d_in[10];

    int n_nodes = in_sizes[0] / 64;
    int n_edges = in_sizes[2] / 64;

    float* out       = (float*)d_out;
    float* feats_out = out;                          // [n_nodes, 64]
    float* e_out     = out + (size_t)n_nodes * 64;   // [n_edges, 64]

    cudaFuncSetAttribute(pnode_kernel, cudaFuncAttributeMaxDynamicSharedMemorySize, P_SMEM);
    cudaFuncSetAttribute(edge_kernel, cudaFuncAttributeMaxDynamicSharedMemorySize, E_SMEM);
    cudaFuncSetAttribute(node_kernel, cudaFuncAttributeMaxDynamicSharedMemorySize, N_SMEM);

    zero_kernel<<<1024, 256>>>(n_nodes);
    pnode_kernel<<<296, 256, P_SMEM>>>(feats, W1e, n_nodes);
    edge_kernel<<<444, 256, E_SMEM>>>(feats, edge_index, edge_attr,
                                      W1e, b1e, W2e, b2e, e_out, n_edges);
    node_kernel<<<148, 256, N_SMEM>>>(feats, W1n, b1n, W2n, b2n,
                                      feats_out, n_nodes);
}

// round 10
// speedup vs baseline: 1.2590x; 1.0507x over previous
#include <cuda_runtime.h>
#include <cuda_bf16.h>
#include <cstdint>

#define MAX_NODES 50000

__device__ float g_agg[MAX_NODES * 64];
__device__ float g_deg[MAX_NODES];
__device__ float g_P[MAX_NODES * 128];   // P[v] = feats[v] @ [W1e[0:64]||W1e[64:128]]

// ---------------- helpers ----------------
__device__ __forceinline__ void mma16816(float d[4], const uint32_t a[4],
                                         const uint32_t b[2]) {
    asm("mma.sync.aligned.m16n8k16.row.col.f32.bf16.bf16.f32 "
        "{%0,%1,%2,%3}, {%4,%5,%6,%7}, {%8,%9}, {%0,%1,%2,%3};"
        : "+f"(d[0]), "+f"(d[1]), "+f"(d[2]), "+f"(d[3])
        : "r"(a[0]), "r"(a[1]), "r"(a[2]), "r"(a[3]), "r"(b[0]), "r"(b[1]));
}

__device__ __forceinline__ void ldsm_x4(uint32_t r[4], uint32_t addr) {
    asm volatile("ldmatrix.sync.aligned.m8n8.x4.shared.b16 {%0,%1,%2,%3}, [%4];"
        : "=r"(r[0]), "=r"(r[1]), "=r"(r[2]), "=r"(r[3]) : "r"(addr));
}

__device__ __forceinline__ void split2(float x0, float x1,
                                       uint32_t& uh, uint32_t& ul) {
    __nv_bfloat162 bh = __floats2bfloat162_rn(x0, x1);
    float2 back = __bfloat1622float2(bh);
    __nv_bfloat162 bl = __floats2bfloat162_rn(x0 - back.x, x1 - back.y);
    uh = *(uint32_t*)&bh;
    ul = *(uint32_t*)&bl;
}

__device__ __forceinline__ void red_add2(float* addr, float a, float b) {
    asm volatile("red.global.add.v2.f32 [%0], {%1, %2};"
                 :: "l"(addr), "f"(a), "f"(b) : "memory");
}

// ---------------- kernel 0: zero scratch ----------------
__global__ void zero_kernel(int n_nodes) {
    int i = blockIdx.x * blockDim.x + threadIdx.x;
    int stride = gridDim.x * blockDim.x;
    int tot = n_nodes * 64;
    for (int k = i; k < tot; k += stride) g_agg[k] = 0.0f;
    for (int k = i; k < n_nodes; k += stride) g_deg[k] = 0.0f;
}

// ======================= P precompute kernel =======================
#define P_SA_HI 0u
#define P_SA_LO 18432u
#define P_SW_HI 36864u
#define P_SW_LO 55296u
#define P_SMEM  73728u

__global__ void __launch_bounds__(256, 2) pnode_kernel(
    const float* __restrict__ feats,
    const float* __restrict__ W1e,
    int n_nodes)
{
    extern __shared__ char smem[];
    uint32_t* sA_hi = (uint32_t*)(smem + P_SA_HI);
    uint32_t* sA_lo = (uint32_t*)(smem + P_SA_LO);

    int tid = threadIdx.x;
    for (int i = tid; i < 128 * 64; i += 256) {
        int n = i & 127, k = i >> 7;
        float w = (n < 64) ? W1e[k * 64 + n] : W1e[(64 + k) * 64 + (n - 64)];
        __nv_bfloat16 wh = __float2bfloat16_rn(w);
        __nv_bfloat16 wl = __float2bfloat16_rn(w - __bfloat162float(wh));
        ((__nv_bfloat16*)(smem + P_SW_HI))[n * 72 + k] = wh;
        ((__nv_bfloat16*)(smem + P_SW_LO))[n * 72 + k] = wl;
    }
    __syncthreads();

    const int warp = tid >> 5, lane = tid & 31;
    const int g = lane >> 2, t = lane & 3;
    const int wr = warp << 4;
    const int row = tid >> 1, half = tid & 1;

    const int r8 = lane & 7;
    const int m01 = (lane >> 3) & 1;
    const int q01 = lane >> 4;
    uint32_t sbase = (uint32_t)__cvta_generic_to_shared(smem);
    uint32_t aHi0 = sbase + P_SA_HI + ((uint32_t)(wr + r8 + m01 * 8) * 36u + q01 * 4u) * 4u;
    uint32_t aLo0 = aHi0 + (P_SA_LO - P_SA_HI);
    uint32_t bOff = ((uint32_t)(q01 * 8 + r8) * 36u + m01 * 4u) * 4u;

    int nTiles = (n_nodes + 127) >> 7;

    for (int tile = blockIdx.x; tile < nTiles; tile += gridDim.x) {
        int nbase = tile << 7;
        {
            int nr = nbase + row;
            int nid = nr < n_nodes ? nr : (n_nodes - 1);
            const float4* src = (const float4*)(feats + (size_t)nid * 64) + half * 8;
            #pragma unroll
            for (int cc = 0; cc < 4; cc++) {
                float4 va = src[cc * 2], vb = src[cc * 2 + 1];
                uint4 uh, ul;
                split2(va.x, va.y, uh.x, ul.x);
                split2(va.z, va.w, uh.y, ul.y);
                split2(vb.x, vb.y, uh.z, ul.z);
                split2(vb.z, vb.w, uh.w, ul.w);
                int col = half * 32 + cc * 8;
                int widx = row * 36 + (col >> 1);
                *(uint4*)(sA_hi + widx) = uh;
                *(uint4*)(sA_lo + widx) = ul;
            }
        }
        __syncwarp();

        float d[16][4];
        #pragma unroll
        for (int i = 0; i < 16; i++)
            #pragma unroll
            for (int j = 0; j < 4; j++) d[i][j] = 0.0f;

        #pragma unroll 1
        for (int kt = 0; kt < 4; kt++) {
            uint32_t ah[4], al[4];
            ldsm_x4(ah, aHi0 + kt * 32u);
            ldsm_x4(al, aLo0 + kt * 32u);
            uint32_t wHi = sbase + P_SW_HI + bOff + kt * 32u;
            uint32_t wLo = sbase + P_SW_LO + bOff + kt * 32u;
            #pragma unroll
            for (int p = 0; p < 8; p++) {
                uint32_t bh[4], bl[4];
                ldsm_x4(bh, wHi + p * 2304u);
                ldsm_x4(bl, wLo + p * 2304u);
                mma16816(d[2 * p],     ah, bh);
                mma16816(d[2 * p + 1], ah, bh + 2);
                mma16816(d[2 * p],     ah, bl);
                mma16816(d[2 * p + 1], ah, bl + 2);
                mma16816(d[2 * p],     al, bh);
                mma16816(d[2 * p + 1], al, bh + 2);
            }
        }

        {
            int r0 = nbase + wr + g, r1 = r0 + 8;
            bool v0 = r0 < n_nodes, v1 = r1 < n_nodes;
            #pragma unroll
            for (int nt = 0; nt < 16; nt++) {
                int c0 = nt * 8 + 2 * t;
                if (v0) *(float2*)(g_P + (size_t)r0 * 128 + c0) =
                            make_float2(d[nt][0], d[nt][1]);
                if (v1) *(float2*)(g_P + (size_t)r1 * 128 + c0) =
                            make_float2(d[nt][2], d[nt][3]);
            }
        }
        __syncwarp();
    }
}

// ======================= edge kernel =======================
#define E_SA_HI   0u
#define E_SA_LO   18432u
#define E_SW1_HI  36864u
#define E_SW1_LO  46080u
#define E_SH_HI   55296u
#define E_SH_LO   73728u
#define E_SW2_HI  92160u
#define E_SW2_LO  101376u
#define E_BIAS1   110592u
#define E_BIAS2   110848u
#define E_SR      111104u
#define E_SC      111616u
#define E_SMEM    112128u

__global__ void __launch_bounds__(256, 2) edge_kernel(
    const float* __restrict__ feats,
    const int* __restrict__ edge_index,
    const float* __restrict__ edge_attr,
    const float* __restrict__ W1e, const float* __restrict__ b1e,
    const float* __restrict__ W2e, const float* __restrict__ b2e,
    float* __restrict__ e_out,
    int n_edges)
{
    extern __shared__ char smem[];
    uint32_t* sA_hi  = (uint32_t*)(smem + E_SA_HI);
    uint32_t* sA_lo  = (uint32_t*)(smem + E_SA_LO);
    uint32_t* sH_hi  = (uint32_t*)(smem + E_SH_HI);
    uint32_t* sH_lo  = (uint32_t*)(smem + E_SH_LO);
    float* bias1 = (float*)(smem + E_BIAS1);
    float* bias2 = (float*)(smem + E_BIAS2);
    int*   sr    = (int*)(smem + E_SR);
    int*   sc    = (int*)(smem + E_SC);

    int tid = threadIdx.x;

    for (int i = tid; i < 64 * 64; i += 256) {
        int k = i >> 6, n = i & 63;
        float w = W1e[(128 + k) * 64 + n];
        __nv_bfloat16 wh = __float2bfloat16_rn(w);
        __nv_bfloat16 wl = __float2bfloat16_rn(w - __bfloat162float(wh));
        ((__nv_bfloat16*)(smem + E_SW1_HI))[n * 72 + k] = wh;
        ((__nv_bfloat16*)(smem + E_SW1_LO))[n * 72 + k] = wl;
    }
    for (int i = tid; i < 64 * 64; i += 256) {
        int k = i >> 6, n = i & 63;
        float w = W2e[i];
        __nv_bfloat16 wh = __float2bfloat16_rn(w);
        __nv_bfloat16 wl = __float2bfloat16_rn(w - __bfloat162float(wh));
        ((__nv_bfloat16*)(smem + E_SW2_HI))[n * 72 + k] = wh;
        ((__nv_bfloat16*)(smem + E_SW2_LO))[n * 72 + k] = wl;
    }
    if (tid < 64) {
        bias1[tid] = b1e[tid];
        bias2[tid] = b2e[tid];
    }
    __syncthreads();

    const int warp = tid >> 5, lane = tid & 31;
    const int g = lane >> 2, t = lane & 3;
    const int wr = warp << 4;
    const int row = tid >> 1, half = tid & 1;

    const int r8 = lane & 7;
    const int m01 = (lane >> 3) & 1;
    const int q01 = lane >> 4;
    uint32_t sbase = (uint32_t)__cvta_generic_to_shared(smem);
    uint32_t fragRow = ((uint32_t)(wr + r8 + m01 * 8) * 36u + q01 * 4u) * 4u;
    uint32_t aHi0 = sbase + E_SA_HI + fragRow;
    uint32_t aLo0 = sbase + E_SA_LO + fragRow;
    uint32_t hHi0 = sbase + E_SH_HI + fragRow;
    uint32_t hLo0 = sbase + E_SH_LO + fragRow;
    uint32_t bOff = ((uint32_t)(q01 * 8 + r8) * 36u + m01 * 4u) * 4u;

    int nTiles = (n_edges + 127) >> 7;

    for (int tile = blockIdx.x; tile < nTiles; tile += gridDim.x) {
        int ebase = tile << 7;

        // ---- gather edge_attr + indices (warp-private rows) ----
        {
            int er = ebase + row;
            bool v = er < n_edges;
            int eid = v ? er : (n_edges - 1);
            if (half == 0) {
                int2 rc = ((const int2*)edge_index)[eid];
                sr[row] = rc.x;
                sc[row] = rc.y;
                if (v) atomicAdd(&g_deg[rc.y], 1.0f);
            }
            const float4* fe = (const float4*)(edge_attr + (size_t)eid * 64) + half * 8;
            #pragma unroll
            for (int cc = 0; cc < 4; cc++) {
                float4 va = fe[cc * 2], vb = fe[cc * 2 + 1];
                uint4 uh, ul;
                split2(va.x, va.y, uh.x, ul.x);
                split2(va.z, va.w, uh.y, ul.y);
                split2(vb.x, vb.y, uh.z, ul.z);
                split2(vb.z, vb.w, uh.w, ul.w);
                int col = half * 32 + cc * 8;
                int widx = row * 36 + (col >> 1);
                *(uint4*)(sA_hi + widx) = uh;
                *(uint4*)(sA_lo + widx) = ul;
            }
        }
        __syncwarp();

        // ---- GEMM1: edge_attr @ W1c, K=64 (LDSM fragments) ----
        float d[8][4];
        #pragma unroll
        for (int i = 0; i < 8; i++)
            #pragma unroll
            for (int j = 0; j < 4; j++) d[i][j] = 0.0f;

        #pragma unroll 1
        for (int kt = 0; kt < 4; kt++) {
            uint32_t ah[4], al[4];
            ldsm_x4(ah, aHi0 + kt * 32u);
            ldsm_x4(al, aLo0 + kt * 32u);
            uint32_t wHi = sbase + E_SW1_HI + bOff + kt * 32u;
            uint32_t wLo = sbase + E_SW1_LO + bOff + kt * 32u;
            #pragma unroll
            for (int p = 0; p < 4; p++) {
                uint32_t bh[4], bl[4];
                ldsm_x4(bh, wHi + p * 2304u);
                ldsm_x4(bl, wLo + p * 2304u);
                mma16816(d[2 * p],     ah, bh);
                mma16816(d[2 * p + 1], ah, bh + 2);
                mma16816(d[2 * p],     ah, bl);
                mma16816(d[2 * p + 1], ah, bl + 2);
                mma16816(d[2 * p],     al, bh);
                mma16816(d[2 * p + 1], al, bh + 2);
            }
        }

        // ---- epilogue 1: h = relu(d + P[r][c] + P[c][64+c] + b1) -> sH ----
        {
            int rr0 = sr[wr + g],     cc0 = sc[wr + g];
            int rr1 = sr[wr + 8 + g], cc1 = sc[wr + 8 + g];
            const float* P0r = g_P + (size_t)rr0 * 128;
            const float* P0c = g_P + (size_t)cc0 * 128 + 64;
            const float* P1r = g_P + (size_t)rr1 * 128;
            const float* P1c = g_P + (size_t)cc1 * 128 + 64;
            #pragma unroll
            for (int nt = 0; nt < 8; nt++) {
                int c0 = nt * 8 + 2 * t;
                float2 pa = *(const float2*)(P0r + c0);
                float2 pb = *(const float2*)(P0c + c0);
                float2 pc_ = *(const float2*)(P1r + c0);
                float2 pd = *(const float2*)(P1c + c0);
                float bb0 = bias1[c0], bb1 = bias1[c0 + 1];
                float h0 = fmaxf(d[nt][0] + pa.x + pb.x + bb0, 0.f);
                float h1 = fmaxf(d[nt][1] + pa.y + pb.y + bb1, 0.f);
                float h2 = fmaxf(d[nt][2] + pc_.x + pd.x + bb0, 0.f);
                float h3 = fmaxf(d[nt][3] + pc_.y + pd.y + bb1, 0.f);
                uint32_t uh, ul;
                int w0 = (wr + g) * 36 + nt * 4 + t;
                split2(h0, h1, uh, ul);
                sH_hi[w0] = uh; sH_lo[w0] = ul;
                split2(h2, h3, uh, ul);
                sH_hi[w0 + 288] = uh; sH_lo[w0 + 288] = ul;
            }
        }
        __syncwarp();

        // ---- GEMM2: K=64 (LDSM fragments) ----
        float d2[8][4];
        #pragma unroll
        for (int i = 0; i < 8; i++)
            #pragma unroll
            for (int j = 0; j < 4; j++) d2[i][j] = 0.0f;

        #pragma unroll 1
        for (int kt = 0; kt < 4; kt++) {
            uint32_t ah[4], al[4];
            ldsm_x4(ah, hHi0 + kt * 32u);
            ldsm_x4(al, hLo0 + kt * 32u);
            uint32_t wHi = sbase + E_SW2_HI + bOff + kt * 32u;
            uint32_t wLo = sbase + E_SW2_LO + bOff + kt * 32u;
            #pragma unroll
            for (int p = 0; p < 4; p++) {
                uint32_t bh[4], bl[4];
                ldsm_x4(bh, wHi + p * 2304u);
                ldsm_x4(bl, wLo + p * 2304u);
                mma16816(d2[2 * p],     ah, bh);
                mma16816(d2[2 * p + 1], ah, bh + 2);
                mma16816(d2[2 * p],     ah, bl);
                mma16816(d2[2 * p + 1], ah, bl + 2);
                mma16816(d2[2 * p],     al, bh);
                mma16816(d2[2 * p + 1], al, bh + 2);
            }
        }

        // ---- epilogue 2: e = D2 + b2 -> e_out + vector red to g_agg ----
        {
            int r0 = ebase + wr + g, r1 = r0 + 8;
            bool v0 = r0 < n_edges, v1 = r1 < n_edges;
            int ca = sc[wr + g], cb = sc[wr + 8 + g];
            #pragma unroll
            for (int nt = 0; nt < 8; nt++) {
                int c0 = nt * 8 + 2 * t;
                float bb0 = bias2[c0], bb1 = bias2[c0 + 1];
                float e0 = d2[nt][0] + bb0, e1 = d2[nt][1] + bb1;
                float e2 = d2[nt][2] + bb0, e3 = d2[nt][3] + bb1;
                if (v0) {
                    *(float2*)(e_out + (size_t)r0 * 64 + c0) = make_float2(e0, e1);
                    red_add2(g_agg + (size_t)ca * 64 + c0, e0, e1);
                }
                if (v1) {
                    *(float2*)(e_out + (size_t)r1 * 64 + c0) = make_float2(e2, e3);
                    red_add2(g_agg + (size_t)cb * 64 + c0, e2, e3);
                }
            }
        }
        __syncwarp();
    }
}

// ======================= node kernel =======================
#define N_SA_HI   0u
#define N_SA_LO   34816u
#define N_SW1_HI  69632u
#define N_SW1_LO  87040u
#define N_SH_HI   104448u
#define N_SH_LO   122880u
#define N_SW2_HI  141312u
#define N_SW2_LO  150528u
#define N_BIAS1   159744u
#define N_BIAS2   160000u
#define N_SMEM    160256u

__global__ void __launch_bounds__(256, 1) node_kernel(
    const float* __restrict__ feats,
    const float* __restrict__ W1n, const float* __restrict__ b1n,
    const float* __restrict__ W2n, const float* __restrict__ b2n,
    float* __restrict__ feats_out,
    int n_nodes)
{
    extern __shared__ char smem[];
    uint32_t* sA_hi  = (uint32_t*)(smem + N_SA_HI);
    uint32_t* sA_lo  = (uint32_t*)(smem + N_SA_LO);
    uint32_t* sH_hi  = (uint32_t*)(smem + N_SH_HI);
    uint32_t* sH_lo  = (uint32_t*)(smem + N_SH_LO);
    float* bias1 = (float*)(smem + N_BIAS1);
    float* bias2 = (float*)(smem + N_BIAS2);

    int tid = threadIdx.x;

    for (int i = tid; i < 128 * 64; i += 256) {
        int k = i >> 6, n = i & 63;
        float w = W1n[i];
        __nv_bfloat16 wh = __float2bfloat16_rn(w);
        __nv_bfloat16 wl = __float2bfloat16_rn(w - __bfloat162float(wh));
        ((__nv_bfloat16*)(smem + N_SW1_HI))[n * 136 + k] = wh;
        ((__nv_bfloat16*)(smem + N_SW1_LO))[n * 136 + k] = wl;
    }
    for (int i = tid; i < 64 * 64; i += 256) {
        int k = i >> 6, n = i & 63;
        float w = W2n[i];
        __nv_bfloat16 wh = __float2bfloat16_rn(w);
        __nv_bfloat16 wl = __float2bfloat16_rn(w - __bfloat162float(wh));
        ((__nv_bfloat16*)(smem + N_SW2_HI))[n * 72 + k] = wh;
        ((__nv_bfloat16*)(smem + N_SW2_LO))[n * 72 + k] = wl;
    }
    if (tid < 64) {
        bias1[tid] = b1n[tid];
        bias2[tid] = b2n[tid];
    }
    __syncthreads();

    const int warp = tid >> 5, lane = tid & 31;
    const int g = lane >> 2, t = lane & 3;
    const int wr = warp << 4;
    const int row = tid >> 1, half = tid & 1;

    const int r8 = lane & 7;
    const int m01 = (lane >> 3) & 1;
    const int q01 = lane >> 4;
    uint32_t sbase = (uint32_t)__cvta_generic_to_shared(smem);
    uint32_t aHi0 = sbase + N_SA_HI + ((uint32_t)(wr + r8 + m01 * 8) * 68u + q01 * 4u) * 4u;
    uint32_t aLo0 = aHi0 + (N_SA_LO - N_SA_HI);
    uint32_t fragRow36 = ((uint32_t)(wr + r8 + m01 * 8) * 36u + q01 * 4u) * 4u;
    uint32_t hHi0 = sbase + N_SH_HI + fragRow36;
    uint32_t hLo0 = sbase + N_SH_LO + fragRow36;
    uint32_t bOff68 = ((uint32_t)(q01 * 8 + r8) * 68u + m01 * 4u) * 4u;
    uint32_t bOff36 = ((uint32_t)(q01 * 8 + r8) * 36u + m01 * 4u) * 4u;

    int nTiles = (n_nodes + 127) >> 7;

    for (int tile = blockIdx.x; tile < nTiles; tile += gridDim.x) {
        int nbase = tile << 7;

        {
            int nr = nbase + row;
            int nid = nr < n_nodes ? nr : (n_nodes - 1);
            const float4* src;
            float scale;
            if (half == 0) {
                src = (const float4*)(feats + (size_t)nid * 64);
                scale = 1.0f;
            } else {
                src = (const float4*)(g_agg + (size_t)nid * 64);
                scale = 1.0f / fmaxf(g_deg[nid], 1.0f);
            }
            #pragma unroll
            for (int cc = 0; cc < 8; cc++) {
                float4 va = src[cc * 2], vb = src[cc * 2 + 1];
                va.x *= scale; va.y *= scale; va.z *= scale; va.w *= scale;
                vb.x *= scale; vb.y *= scale; vb.z *= scale; vb.w *= scale;
                uint4 uh, ul;
                split2(va.x, va.y, uh.x, ul.x);
                split2(va.z, va.w, uh.y, ul.y);
                split2(vb.x, vb.y, uh.z, ul.z);
                split2(vb.z, vb.w, uh.w, ul.w);
                int col = half * 64 + cc * 8;
                int widx = row * 68 + (col >> 1);
                *(uint4*)(sA_hi + widx) = uh;
                *(uint4*)(sA_lo + widx) = ul;
            }
        }
        __syncwarp();

        float d[8][4];
        #pragma unroll
        for (int i = 0; i < 8; i++)
            #pragma unroll
            for (int j = 0; j < 4; j++) d[i][j] = 0.0f;

        #pragma unroll 1
        for (int kt = 0; kt < 8; kt++) {
            uint32_t ah[4], al[4];
            ldsm_x4(ah, aHi0 + kt * 32u);
            ldsm_x4(al, aLo0 + kt * 32u);
            uint32_t wHi = sbase + N_SW1_HI + bOff68 + kt * 32u;
            uint32_t wLo = sbase + N_SW1_LO + bOff68 + kt * 32u;
            #pragma unroll
            for (int p = 0; p < 4; p++) {
                uint32_t bh[4], bl[4];
                ldsm_x4(bh, wHi + p * 4352u);
                ldsm_x4(bl, wLo + p * 4352u);
                mma16816(d[2 * p],     ah, bh);
                mma16816(d[2 * p + 1], ah, bh + 2);
                mma16816(d[2 * p],     ah, bl);
                mma16816(d[2 * p + 1], ah, bl + 2);
                mma16816(d[2 * p],     al, bh);
                mma16816(d[2 * p + 1], al, bh + 2);
            }
        }

        #pragma unroll
        for (int nt = 0; nt < 8; nt++) {
            int c0 = nt * 8 + 2 * t;
            float bb0 = bias1[c0], bb1 = bias1[c0 + 1];
            float h0 = fmaxf(d[nt][0] + bb0, 0.f), h1 = fmaxf(d[nt][1] + bb1, 0.f);
            float h2 = fmaxf(d[nt][2] + bb0, 0.f), h3 = fmaxf(d[nt][3] + bb1, 0.f);
            uint32_t uh, ul;
            int w0 = (wr + g) * 36 + nt * 4 + t;
            split2(h0, h1, uh, ul);
            sH_hi[w0] = uh; sH_lo[w0] = ul;
            split2(h2, h3, uh, ul);
            sH_hi[w0 + 288] = uh; sH_lo[w0 + 288] = ul;
        }
        __syncwarp();

        float d2[8][4];
        #pragma unroll
        for (int i = 0; i < 8; i++)
            #pragma unroll
            for (int j = 0; j < 4; j++) d2[i][j] = 0.0f;

        #pragma unroll 1
        for (int kt = 0; kt < 4; kt++) {
            uint32_t ah[4], al[4];
            ldsm_x4(ah, hHi0 + kt * 32u);
            ldsm_x4(al, hLo0 + kt * 32u);
            uint32_t wHi = sbase + N_SW2_HI + bOff36 + kt * 32u;
            uint32_t wLo = sbase + N_SW2_LO + bOff36 + kt * 32u;
            #pragma unroll
            for (int p = 0; p < 4; p++) {
                uint32_t bh[4], bl[4];
                ldsm_x4(bh, wHi + p * 2304u);
                ldsm_x4(bl, wLo + p * 2304u);
                mma16816(d2[2 * p],     ah, bh);
                mma16816(d2[2 * p + 1], ah, bh + 2);
                mma16816(d2[2 * p],     ah, bl);
                mma16816(d2[2 * p + 1], ah, bl + 2);
                mma16816(d2[2 * p],     al, bh);
                mma16816(d2[2 * p + 1], al, bh + 2);
            }
        }

        {
            int r0 = nbase + wr + g, r1 = r0 + 8;
            bool v0 = r0 < n_nodes, v1 = r1 < n_nodes;
            #pragma unroll
            for (int nt = 0; nt < 8; nt++) {
                int c0 = nt * 8 + 2 * t;
                float bb0 = bias2[c0], bb1 = bias2[c0 + 1];
                if (v0)
                    *(float2*)(feats_out + (size_t)r0 * 64 + c0) =
                        make_float2(d2[nt][0] + bb0, d2[nt][1] + bb1);
                if (v1)
                    *(float2*)(feats_out + (size_t)r1 * 64 + c0) =
                        make_float2(d2[nt][2] + bb0, d2[nt][3] + bb1);
            }
        }
        __syncwarp();
    }
}

// ======================= launch =======================
extern "C" void kernel_launch(void* const* d_in, const int* in_sizes, int n_in,
                              void* d_out, int out_size) {
    const float* feats      = (const float*)d_in[0];
    const int*   edge_index = (const int*)d_in[1];
    const float* edge_attr  = (const float*)d_in[2];
    const float* W1e        = (const float*)d_in[3];
    const float* b1e        = (const float*)d_in[4];
    const float* W2e        = (const float*)d_in[5];
    const float* b2e        = (const float*)d_in[6];
    const float* W1n        = (const float*)d_in[7];
    const float* b1n        = (const float*)d_in[8];
    const float* W2n        = (const float*)d_in[9];
    const float* b2n        = (const float*)d_in[10];

    int n_nodes = in_sizes[0] / 64;
    int n_edges = in_sizes[2] / 64;

    float* out       = (float*)d_out;
    float* feats_out = out;                          // [n_nodes, 64]
    float* e_out     = out + (size_t)n_nodes * 64;   // [n_edges, 64]

    cudaFuncSetAttribute(pnode_kernel, cudaFuncAttributeMaxDynamicSharedMemorySize, P_SMEM);
    cudaFuncSetAttribute(edge_kernel, cudaFuncAttributeMaxDynamicSharedMemorySize, E_SMEM);
    cudaFuncSetAttribute(node_kernel, cudaFuncAttributeMaxDynamicSharedMemorySize, N_SMEM);

    zero_kernel<<<1024, 256>>>(n_nodes);
    pnode_kernel<<<296, 256, P_SMEM>>>(feats, W1e, n_nodes);
    edge_kernel<<<296, 256, E_SMEM>>>(feats, edge_index, edge_attr,
                                      W1e, b1e, W2e, b2e, e_out, n_edges);
    node_kernel<<<148, 256, N_SMEM>>>(feats, W1n, b1n, W2n, b2n,
                                      feats_out, n_nodes);
}